// round 8
// baseline (speedup 1.0000x reference)
#include <cuda_runtime.h>
#include <cuda_bf16.h>
#include <math.h>
#include <stdint.h>

typedef unsigned long long ull;

#define BATCH 64
#define LSEQ  2048
#define DMODEL 256
#define DU 1024
#define HHID 128
#define NTOK (BATCH*LSEQ)
#define LTOK 128
#define LTILE (NTOK/LTOK)   // 1024

// ---------------- device scratch ----------------
__device__ __nv_bfloat16 g_hev_hi[(size_t)NTOK * DMODEL];
__device__ __nv_bfloat16 g_hev_lo[(size_t)NTOK * DMODEL];
__device__ __nv_bfloat16 g_Wa_hi[DU * DMODEL];
__device__ __nv_bfloat16 g_Wa_lo[DU * DMODEL];
__device__ __nv_bfloat16 g_W1_hi[HHID * DMODEL];
__device__ __nv_bfloat16 g_W1_lo[HHID * DMODEL];
__device__ float g_cvec[HHID];
__device__ float g_aval[NTOK];
__device__ int   g_active[NTOK];
__device__ int   g_count[BATCH];
__device__ int   g_tile;

// ---------------- helpers ----------------
__device__ __forceinline__ float lrelu(float x) { return x > 0.f ? x : 0.2f * x; }

__device__ __forceinline__ uint32_t smem_u32(const void* p) {
    uint32_t a;
    asm("{ .reg .u64 t; cvta.to.shared.u64 t, %1; cvt.u32.u64 %0, t; }" : "=r"(a) : "l"(p));
    return a;
}
__device__ __forceinline__ void mma16816(float* d, const uint32_t* a, const uint32_t* b) {
    asm volatile(
        "mma.sync.aligned.m16n8k16.row.col.f32.bf16.bf16.f32 "
        "{%0,%1,%2,%3}, {%4,%5,%6,%7}, {%8,%9}, {%0,%1,%2,%3};"
        : "+f"(d[0]), "+f"(d[1]), "+f"(d[2]), "+f"(d[3])
        : "r"(a[0]), "r"(a[1]), "r"(a[2]), "r"(a[3]), "r"(b[0]), "r"(b[1]));
}
__device__ __forceinline__ void ldsm4(uint32_t* r, uint32_t addr) {
    asm volatile("ldmatrix.sync.aligned.m8n8.x4.shared.b16 {%0,%1,%2,%3}, [%4];"
        : "=r"(r[0]), "=r"(r[1]), "=r"(r[2]), "=r"(r[3]) : "r"(addr));
}
__device__ __forceinline__ void cp16(uint32_t dst, const void* src) {
    asm volatile("cp.async.cg.shared.global [%0], [%1], 16;" :: "r"(dst), "l"(src));
}
#define CP_COMMIT() asm volatile("cp.async.commit_group;" ::: "memory")
#define CP_WAIT0()  asm volatile("cp.async.wait_group 0;" ::: "memory")

// ---------------- kernel 0a: constant head bias ----------------
__global__ void k_setup(const float* __restrict__ Ws1, const float* __restrict__ bs1,
                        const float* __restrict__ vn) {
    int h = blockIdx.x * (blockDim.x >> 5) + (threadIdx.x >> 5);
    int l = threadIdx.x & 31;
    if (h >= HHID) return;
    const float* row = Ws1 + (size_t)h * 512 + 256;
    float s = 0.f;
#pragma unroll
    for (int d = l; d < 256; d += 32) s += row[d] * vn[d];
#pragma unroll
    for (int off = 16; off; off >>= 1) s += __shfl_xor_sync(0xffffffffu, s, off);
    if (l == 0) g_cvec[h] = s + bs1[h];
}

// ---------------- kernel 0b: weights -> bf16 hi/lo, zero outputs ----------------
__global__ void k_prep(const float* __restrict__ Wa, const float* __restrict__ Ws1,
                       float* __restrict__ out_u) {
    int idx = blockIdx.x * blockDim.x + threadIdx.x;
    if (idx < DU * DMODEL) {
        float v = Wa[idx];
        __nv_bfloat16 hi = __float2bfloat16(v);
        __nv_bfloat16 lo = __float2bfloat16(v - __bfloat162float(hi));
        g_Wa_hi[idx] = hi;
        g_Wa_lo[idx] = lo;
    }
    if (idx < HHID * DMODEL) {
        int h = idx >> 8, d = idx & 255;
        float v = Ws1[h * 512 + d];
        __nv_bfloat16 hi = __float2bfloat16(v);
        __nv_bfloat16 lo = __float2bfloat16(v - __bfloat162float(hi));
        g_W1_hi[idx] = hi;
        g_W1_lo[idx] = lo;
    }
    if (idx < BATCH * DU) out_u[idx] = 0.f;
    if (idx < BATCH) g_count[idx] = 0;
    if (idx == 0) g_tile = 0;
}

// ---------------- kernel 1a: embedding + trig -> bf16 hi/lo ----------------
__global__ __launch_bounds__(256) void k_emb(
    const int* __restrict__ q_seq, const int* __restrict__ r_seq,
    const float* __restrict__ t_seq,
    const float* __restrict__ q_tab, const float* __restrict__ r_tab)
{
    __shared__ int sq[16], sr[16];
    __shared__ float st[16];
    const int tid = threadIdx.x;
    const int tok0 = blockIdx.x * 16;
    if (tid < 16) {
        sq[tid] = q_seq[tok0 + tid];
        sr[tid] = r_seq[tok0 + tid];
        st[tid] = t_seq[tok0 + tid];
    }
    __syncthreads();
    const int d = tid;
    const float ddf  = (float)(d & 127);
    const float freq = expf(ddf * (-9.2103403719761836f / 128.f));
    const bool is_sin = d < 128;
    __nv_bfloat16* ghi = g_hev_hi + (size_t)tok0 * 256 + d;
    __nv_bfloat16* glo = g_hev_lo + (size_t)tok0 * 256 + d;
#pragma unroll 4
    for (int t = 0; t < 16; ++t) {
        float arg = st[t] * freq;
        float tv  = is_sin ? sinf(arg) : cosf(arg);
        float val = q_tab[(size_t)sq[t] * 256 + d] + r_tab[sr[t] * 256 + d] + tv;
        __nv_bfloat16 hb = __float2bfloat16(val);
        ghi[(size_t)t * 256] = hb;
        glo[(size_t)t * 256] = __float2bfloat16(val - __bfloat162float(hb));
    }
}

// ---------------- kernel 1b: HMMA logits + compaction (unchanged from R7) ----------------
#define LW_OFF   0
#define LW_TERM  67584
#define LH_OFF   135168
#define LH_TERM  34816
#define LSLOG    204800
#define LSTILE   205824
#define SMEM_LG  205952

__global__ __launch_bounds__(256, 1) void k_logits_mma(
    const float* __restrict__ mask, const float* __restrict__ Ws2,
    const float* __restrict__ bs2, float* __restrict__ outA)
{
    extern __shared__ char smem[];
    const uint32_t sb = smem_u32(smem);
    const int tid  = threadIdx.x;
    const int wid  = tid >> 5;
    const int lane = tid & 31;
    const int gid  = lane >> 2;
    const int warpM = wid >> 2;
    const int warpN = wid & 3;

    float* slog  = (float*)(smem + LSLOG);
    int*   stile = (int*)(smem + LSTILE);

    for (int i = tid; i < 8192; i += 256) {
        int term = i >> 12;
        int r = (i >> 5) & 127;
        int c = i & 31;
        const __nv_bfloat16* src = term ? g_W1_lo : g_W1_hi;
        uint4 v = ((const uint4*)(src + ((size_t)r << 8)))[c];
        *(uint4*)(smem + LW_OFF + term * LW_TERM + r * 528 + c * 16) = v;
    }

    float wc[4][2], cv[4][2];
#pragma unroll
    for (int m = 0; m < 4; ++m) {
        int h0 = warpM * 64 + m * 16 + gid;
        wc[m][0] = Ws2[h0];     wc[m][1] = Ws2[h0 + 8];
        cv[m][0] = g_cvec[h0];  cv[m][1] = g_cvec[h0 + 8];
    }
    const float b2v = bs2[0];

    const int st_term = tid >> 7;
    const int st_row  = tid & 127;

    const uint32_t w_ld = sb + LW_OFF + (uint32_t)((lane & 15) * 528 + (lane >> 4) * 16);
    const uint32_t h_ld = sb + LH_OFF +
        (uint32_t)((warpN * 32 + (lane & 15)) * 272 + (lane >> 4) * 16);

    if (tid == 0) *stile = atomicAdd(&g_tile, 1);
    __syncthreads();
    int tile = *stile;

    uint4 RA[16];
    if (tile < LTILE) {
        const uint4* p = (const uint4*)((st_term ? g_hev_lo : g_hev_hi)
                        + ((size_t)(tile * LTOK + st_row) << 8));
#pragma unroll
        for (int c = 0; c < 16; ++c) RA[c] = p[c];
    }

    while (tile < LTILE) {
        const int tok0 = tile * LTOK;
        const int b    = tok0 >> 11;

        {
            char* dst = smem + LH_OFF + st_term * LH_TERM + st_row * 272;
#pragma unroll
            for (int c = 0; c < 16; ++c) *(uint4*)(dst + c * 16) = RA[c];
        }
        __syncthreads();

        {
            const uint4* p = (const uint4*)((st_term ? g_hev_lo : g_hev_hi)
                            + ((size_t)(tok0 + st_row) << 8) + 128);
#pragma unroll
            for (int c = 0; c < 16; ++c) RA[c] = p[c];
        }

        float C[4][4][4];
#pragma unroll
        for (int m = 0; m < 4; ++m)
#pragma unroll
            for (int n = 0; n < 4; ++n)
#pragma unroll
                for (int k = 0; k < 4; ++k) C[m][n][k] = 0.f;

#pragma unroll
        for (int ks = 0; ks < 8; ++ks) {
            uint32_t ah[4][4], al[4][4], bh[4][2], bl[4][2], tmp[4];
#pragma unroll
            for (int m = 0; m < 4; ++m) {
                uint32_t ro = (uint32_t)((warpM * 64 + m * 16) * 528 + ks * 32);
                ldsm4(ah[m], w_ld + ro);
                ldsm4(al[m], w_ld + LW_TERM + ro);
            }
#pragma unroll
            for (int nc = 0; nc < 2; ++nc) {
                uint32_t no = (uint32_t)(nc * 16 * 272 + ks * 32);
                ldsm4(tmp, h_ld + no);
                bh[2*nc][0] = tmp[0]; bh[2*nc+1][0] = tmp[1];
                bh[2*nc][1] = tmp[2]; bh[2*nc+1][1] = tmp[3];
                ldsm4(tmp, h_ld + LH_TERM + no);
                bl[2*nc][0] = tmp[0]; bl[2*nc+1][0] = tmp[1];
                bl[2*nc][1] = tmp[2]; bl[2*nc+1][1] = tmp[3];
            }
#pragma unroll
            for (int m = 0; m < 4; ++m)
#pragma unroll
                for (int n = 0; n < 4; ++n) mma16816(C[m][n], ah[m], bh[n]);
#pragma unroll
            for (int m = 0; m < 4; ++m)
#pragma unroll
                for (int n = 0; n < 4; ++n) mma16816(C[m][n], ah[m], bl[n]);
#pragma unroll
            for (int m = 0; m < 4; ++m)
#pragma unroll
                for (int n = 0; n < 4; ++n) mma16816(C[m][n], al[m], bh[n]);
        }
        __syncthreads();

        {
            char* dst = smem + LH_OFF + st_term * LH_TERM + st_row * 272;
#pragma unroll
            for (int c = 0; c < 16; ++c) *(uint4*)(dst + c * 16) = RA[c];
        }
        if (tid == 0) *stile = atomicAdd(&g_tile, 1);
        __syncthreads();

#pragma unroll
        for (int ks = 0; ks < 8; ++ks) {
            uint32_t ah[4][4], al[4][4], bh[4][2], bl[4][2], tmp[4];
#pragma unroll
            for (int m = 0; m < 4; ++m) {
                uint32_t ro = (uint32_t)((warpM * 64 + m * 16) * 528 + (8 + ks) * 32);
                ldsm4(ah[m], w_ld + ro);
                ldsm4(al[m], w_ld + LW_TERM + ro);
            }
#pragma unroll
            for (int nc = 0; nc < 2; ++nc) {
                uint32_t no = (uint32_t)(nc * 16 * 272 + ks * 32);
                ldsm4(tmp, h_ld + no);
                bh[2*nc][0] = tmp[0]; bh[2*nc+1][0] = tmp[1];
                bh[2*nc][1] = tmp[2]; bh[2*nc+1][1] = tmp[3];
                ldsm4(tmp, h_ld + LH_TERM + no);
                bl[2*nc][0] = tmp[0]; bl[2*nc+1][0] = tmp[1];
                bl[2*nc][1] = tmp[2]; bl[2*nc+1][1] = tmp[3];
            }
#pragma unroll
            for (int m = 0; m < 4; ++m)
#pragma unroll
                for (int n = 0; n < 4; ++n) mma16816(C[m][n], ah[m], bh[n]);
#pragma unroll
            for (int m = 0; m < 4; ++m)
#pragma unroll
                for (int n = 0; n < 4; ++n) mma16816(C[m][n], ah[m], bl[n]);
#pragma unroll
            for (int m = 0; m < 4; ++m)
#pragma unroll
                for (int n = 0; n < 4; ++n) mma16816(C[m][n], al[m], bh[n]);
        }

        const int nt = *stile;
        if (nt < LTILE) {
            const uint4* p = (const uint4*)((st_term ? g_hev_lo : g_hev_hi)
                            + ((size_t)(nt * LTOK + st_row) << 8));
#pragma unroll
            for (int c = 0; c < 16; ++c) RA[c] = p[c];
        }

        {
            float tsum[4][2];
#pragma unroll
            for (int n = 0; n < 4; ++n) { tsum[n][0] = 0.f; tsum[n][1] = 0.f; }
#pragma unroll
            for (int m = 0; m < 4; ++m)
#pragma unroll
                for (int n = 0; n < 4; ++n) {
                    tsum[n][0] += wc[m][0] * lrelu(C[m][n][0] + cv[m][0])
                                + wc[m][1] * lrelu(C[m][n][2] + cv[m][1]);
                    tsum[n][1] += wc[m][0] * lrelu(C[m][n][1] + cv[m][0])
                                + wc[m][1] * lrelu(C[m][n][3] + cv[m][1]);
                }
#pragma unroll
            for (int n = 0; n < 4; ++n)
#pragma unroll
                for (int k2 = 0; k2 < 2; ++k2) {
                    float v = tsum[n][k2];
                    v += __shfl_xor_sync(0xffffffffu, v, 4);
                    v += __shfl_xor_sync(0xffffffffu, v, 8);
                    v += __shfl_xor_sync(0xffffffffu, v, 16);
                    tsum[n][k2] = v;
                }
            if (lane < 4) {
#pragma unroll
                for (int n = 0; n < 4; ++n) {
                    int t = warpN * 32 + n * 8 + 2 * lane;
                    slog[warpM * 128 + t]     = tsum[n][0];
                    slog[warpM * 128 + t + 1] = tsum[n][1];
                }
            }
        }
        __syncthreads();

        if (tid < 128) {
            float logit = slog[tid] + slog[128 + tid] + b2v;
            float a = mask[tok0 + tid] / (1.f + expf(-logit * 100.f));
            outA[tok0 + tid]   = a;
            g_aval[tok0 + tid] = a;
            bool act = a > 1e-10f;
            unsigned mb = __ballot_sync(0xffffffffu, act);
            int cntw = __popc(mb);
            int base = 0;
            if (lane == 0 && cntw) base = atomicAdd(&g_count[b], cntw);
            base = __shfl_sync(0xffffffffu, base, 0);
            if (act) {
                int slot = base + __popc(mb & ((1u << lane) - 1u));
                g_active[b * LSEQ + slot] = (tok0 & (LSEQ - 1)) + tid;
            }
        }
        tile = nt;
        __syncthreads();
    }
}

// ---------------- kernel 2: single-wave HMMA aggregator (4 batches/block) ----------------
// grid (8 u-chunks, 16) = 128 blocks; B staged ONCE per block, reused for 4 batches.
#define KA_B_OFF   0
#define KA_A_OFF   135168
#define KA_ABUF    34816
#define KA_ATERM   17408
#define KA_SA_OFF  204800
#define KA_STOK_OFF 205312
#define SMEM_AGG   205824

__global__ __launch_bounds__(256, 1) void k_agg_p(const float* __restrict__ ba,
                                                  float* __restrict__ out_u)
{
    extern __shared__ char smem[];
    const uint32_t sb = smem_u32(smem);
    const int tid  = threadIdx.x;
    const int wid  = tid >> 5;
    const int lane = tid & 31;
    const int gid  = lane >> 2;
    const int colbase = blockIdx.x * 128;
    const int warpM = wid >> 2;
    const int warpN = wid & 3;

    float* sa   = (float*)(smem + KA_SA_OFF);
    int*   stok = (int*)(smem + KA_STOK_OFF);

    // stage B (Wa slice hi+lo) once for all 4 batches
    for (int i = tid; i < 8192; i += 256) {
        int term = i >> 12;
        int r = (i >> 5) & 127;
        int c = i & 31;
        const __nv_bfloat16* src = term ? g_Wa_lo : g_Wa_hi;
        uint4 v = ((const uint4*)(src + ((size_t)(colbase + r) << 8)))[c];
        *(uint4*)(smem + KA_B_OFF + term * 67584 + r * 528 + c * 16) = v;
    }

    float ban0[4], ban1[4];
#pragma unroll
    for (int n = 0; n < 4; ++n) {
        int c0 = colbase + warpN * 32 + n * 8 + 2 * (lane & 3);
        ban0[n] = ba[c0];
        ban1[n] = ba[c0 + 1];
    }

    const uint32_t a_ld_base = sb + KA_A_OFF
        + (uint32_t)((lane & 15) * 272 + (lane >> 4) * 16);
    const uint32_t b_ld_base = sb + KA_B_OFF
        + (uint32_t)((warpN * 32 + (lane & 15)) * 528 + (lane >> 4) * 16);

    for (int bi = 0; bi < 4; ++bi) {
        const int b = blockIdx.y * 4 + bi;
        const int cnt = g_count[b];
        const int ntile = (cnt + 63) >> 6;

        __syncthreads();   // protect stok/sa reuse across batches (and after B stage)

        float colacc[4][2];
#pragma unroll
        for (int n = 0; n < 4; ++n) { colacc[n][0] = 0.f; colacc[n][1] = 0.f; }

        if (tid < 64 && ntile > 0) {
            int tok = (tid < cnt) ? g_active[(b << 11) + tid] : 0;
            stok[tid] = tok;
            sa[tid]   = (tid < cnt) ? g_aval[(b << 11) + tok] : 0.f;
        }
        __syncthreads();

        if (ntile > 0) {
#pragma unroll
            for (int i = 0; i < 8; ++i) {
                int idx = tid + i * 256;
                int term = idx >> 10;
                int row  = (idx >> 4) & 63;
                int c    = idx & 15;
                const __nv_bfloat16* src = term ? g_hev_lo : g_hev_hi;
                cp16(sb + KA_A_OFF + (uint32_t)(term * KA_ATERM + row * 272 + c * 16),
                     src + (((size_t)(b << 11) + stok[row]) << 8) + (c << 3));
            }
            CP_COMMIT();
        }

        int cur = 0;
        for (int t = 0; t < ntile; ++t, cur ^= 1) {
            const int nxt = cur ^ 1;
            if (tid < 64 && t + 1 < ntile) {
                int slot = ((t + 1) << 6) + tid;
                int tok = (slot < cnt) ? g_active[(b << 11) + slot] : 0;
                stok[nxt * 64 + tid] = tok;
                sa[nxt * 64 + tid]   = (slot < cnt) ? g_aval[(b << 11) + tok] : 0.f;
            }
            CP_WAIT0();
            __syncthreads();

#pragma unroll
            for (int i = 0; i < 8; ++i) {
                int idx = tid + i * 256;
                int term = idx >> 10;
                int row  = (idx >> 4) & 63;
                int c    = idx & 15;
                const __nv_bfloat16* src = term ? g_hev_lo : g_hev_hi;
                cp16(sb + KA_A_OFF + KA_ABUF
                         + (uint32_t)(term * KA_ATERM + row * 272 + c * 16),
                     src + (((size_t)(b << 11) + stok[cur * 64 + row]) << 8) + 128 + (c << 3));
            }
            CP_COMMIT();

            float C[2][4][4];
#pragma unroll
            for (int m = 0; m < 2; ++m)
#pragma unroll
                for (int n = 0; n < 4; ++n)
#pragma unroll
                    for (int k = 0; k < 4; ++k) C[m][n][k] = 0.f;

#pragma unroll
            for (int ks = 0; ks < 8; ++ks) {
                uint32_t ah[2][4], al[2][4], bh[4][2], bl[4][2], tmp[4];
#pragma unroll
                for (int m = 0; m < 2; ++m) {
                    uint32_t ro = (uint32_t)((warpM * 32 + m * 16) * 272 + ks * 32);
                    ldsm4(ah[m], a_ld_base + ro);
                    ldsm4(al[m], a_ld_base + KA_ATERM + ro);
                }
#pragma unroll
                for (int nc = 0; nc < 2; ++nc) {
                    uint32_t no = (uint32_t)(nc * 16 * 528 + ks * 32);
                    ldsm4(tmp, b_ld_base + no);
                    bh[2*nc][0] = tmp[0]; bh[2*nc+1][0] = tmp[1];
                    bh[2*nc][1] = tmp[2]; bh[2*nc+1][1] = tmp[3];
                    ldsm4(tmp, b_ld_base + 67584 + no);
                    bl[2*nc][0] = tmp[0]; bl[2*nc+1][0] = tmp[1];
                    bl[2*nc][1] = tmp[2]; bl[2*nc+1][1] = tmp[3];
                }
#pragma unroll
                for (int m = 0; m < 2; ++m)
#pragma unroll
                    for (int n = 0; n < 4; ++n) mma16816(C[m][n], ah[m], bh[n]);
#pragma unroll
                for (int m = 0; m < 2; ++m)
#pragma unroll
                    for (int n = 0; n < 4; ++n) mma16816(C[m][n], ah[m], bl[n]);
#pragma unroll
                for (int m = 0; m < 2; ++m)
#pragma unroll
                    for (int n = 0; n < 4; ++n) mma16816(C[m][n], al[m], bh[n]);
            }

            CP_WAIT0();
            __syncthreads();

            if (t + 1 < ntile) {
#pragma unroll
                for (int i = 0; i < 8; ++i) {
                    int idx = tid + i * 256;
                    int term = idx >> 10;
                    int row  = (idx >> 4) & 63;
                    int c    = idx & 15;
                    const __nv_bfloat16* src = term ? g_hev_lo : g_hev_hi;
                    cp16(sb + KA_A_OFF + (uint32_t)(term * KA_ATERM + row * 272 + c * 16),
                         src + (((size_t)(b << 11) + stok[nxt * 64 + row]) << 8) + (c << 3));
                }
                CP_COMMIT();
            }

#pragma unroll
            for (int ks = 0; ks < 8; ++ks) {
                uint32_t ah[2][4], al[2][4], bh[4][2], bl[4][2], tmp[4];
#pragma unroll
                for (int m = 0; m < 2; ++m) {
                    uint32_t ro = (uint32_t)((warpM * 32 + m * 16) * 272 + ks * 32);
                    ldsm4(ah[m], a_ld_base + KA_ABUF + ro);
                    ldsm4(al[m], a_ld_base + KA_ABUF + KA_ATERM + ro);
                }
#pragma unroll
                for (int nc = 0; nc < 2; ++nc) {
                    uint32_t no = (uint32_t)(nc * 16 * 528 + 256 + ks * 32);
                    ldsm4(tmp, b_ld_base + no);
                    bh[2*nc][0] = tmp[0]; bh[2*nc+1][0] = tmp[1];
                    bh[2*nc][1] = tmp[2]; bh[2*nc+1][1] = tmp[3];
                    ldsm4(tmp, b_ld_base + 67584 + no);
                    bl[2*nc][0] = tmp[0]; bl[2*nc+1][0] = tmp[1];
                    bl[2*nc][1] = tmp[2]; bl[2*nc+1][1] = tmp[3];
                }
#pragma unroll
                for (int m = 0; m < 2; ++m)
#pragma unroll
                    for (int n = 0; n < 4; ++n) mma16816(C[m][n], ah[m], bh[n]);
#pragma unroll
                for (int m = 0; m < 2; ++m)
#pragma unroll
                    for (int n = 0; n < 4; ++n) mma16816(C[m][n], ah[m], bl[n]);
#pragma unroll
                for (int m = 0; m < 2; ++m)
#pragma unroll
                    for (int n = 0; n < 4; ++n) mma16816(C[m][n], al[m], bh[n]);
            }

#pragma unroll
            for (int m = 0; m < 2; ++m) {
                float a0 = sa[cur * 64 + warpM * 32 + m * 16 + gid];
                float a1 = sa[cur * 64 + warpM * 32 + m * 16 + gid + 8];
#pragma unroll
                for (int n = 0; n < 4; ++n) {
                    colacc[n][0] += a0 * lrelu(C[m][n][0] + ban0[n])
                                  + a1 * lrelu(C[m][n][2] + ban0[n]);
                    colacc[n][1] += a0 * lrelu(C[m][n][1] + ban1[n])
                                  + a1 * lrelu(C[m][n][3] + ban1[n]);
                }
            }
        }

#pragma unroll
        for (int n = 0; n < 4; ++n)
#pragma unroll
            for (int j = 0; j < 2; ++j) {
                float v = colacc[n][j];
                v += __shfl_xor_sync(0xffffffffu, v, 4);
                v += __shfl_xor_sync(0xffffffffu, v, 8);
                v += __shfl_xor_sync(0xffffffffu, v, 16);
                colacc[n][j] = v;
            }
        if (lane < 4) {
#pragma unroll
            for (int n = 0; n < 4; ++n) {
                int c0 = colbase + warpN * 32 + n * 8 + 2 * lane;
                atomicAdd(&out_u[b * DU + c0],     colacc[n][0]);
                atomicAdd(&out_u[b * DU + c0 + 1], colacc[n][1]);
            }
        }
    }
}

// ---------------- launch ----------------
extern "C" void kernel_launch(void* const* d_in, const int* in_sizes, int n_in,
                              void* d_out, int out_size) {
    const int*   q_seq = (const int*)d_in[0];
    const int*   r_seq = (const int*)d_in[1];
    const float* t_seq = (const float*)d_in[2];
    const float* mask  = (const float*)d_in[3];
    const float* q_tab = (const float*)d_in[4];
    const float* r_tab = (const float*)d_in[5];
    const float* vn    = (const float*)d_in[6];
    const float* Ws1   = (const float*)d_in[7];
    const float* bs1   = (const float*)d_in[8];
    const float* Ws2   = (const float*)d_in[9];
    const float* bs2   = (const float*)d_in[10];
    const float* Wa    = (const float*)d_in[11];
    const float* ba    = (const float*)d_in[12];

    float* out_u = (float*)d_out;            // (64, 1024)
    float* outA  = out_u + BATCH * DU;       // (64, 2048)

    k_setup<<<4, 1024>>>(Ws1, bs1, vn);
    k_prep<<<(DU * DMODEL + 255) / 256, 256>>>(Wa, Ws1, out_u);

    k_emb<<<NTOK / 16, 256>>>(q_seq, r_seq, t_seq, q_tab, r_tab);

    cudaFuncSetAttribute(k_logits_mma, cudaFuncAttributeMaxDynamicSharedMemorySize, SMEM_LG);
    k_logits_mma<<<148, 256, SMEM_LG>>>(mask, Ws2, bs2, outA);

    cudaFuncSetAttribute(k_agg_p, cudaFuncAttributeMaxDynamicSharedMemorySize, SMEM_AGG);
    k_agg_p<<<dim3(8, 16), 256, SMEM_AGG>>>(ba, out_u);
}

// round 9
// speedup vs baseline: 1.0176x; 1.0176x over previous
#include <cuda_runtime.h>
#include <cuda_bf16.h>
#include <math.h>
#include <stdint.h>

typedef unsigned long long ull;

#define BATCH 64
#define LSEQ  2048
#define DMODEL 256
#define DU 1024
#define HHID 128
#define NTOK (BATCH*LSEQ)
#define LTOK 128
#define LTILE (NTOK/LTOK)   // 1024

// ---------------- device scratch ----------------
__device__ __nv_bfloat16 g_hev_hi[(size_t)NTOK * DMODEL];
__device__ __nv_bfloat16 g_hev_lo[(size_t)NTOK * DMODEL];
__device__ __nv_bfloat16 g_Wa_hi[DU * DMODEL];
__device__ __nv_bfloat16 g_Wa_lo[DU * DMODEL];
__device__ __nv_bfloat16 g_W1_hi[HHID * DMODEL];
__device__ __nv_bfloat16 g_W1_lo[HHID * DMODEL];
__device__ float g_cvec[HHID];
__device__ float g_aval[NTOK];
__device__ int   g_active[NTOK];
__device__ int   g_count[BATCH];
__device__ int   g_tile;

// ---------------- helpers ----------------
__device__ __forceinline__ float lrelu(float x) { return x > 0.f ? x : 0.2f * x; }

__device__ __forceinline__ uint32_t smem_u32(const void* p) {
    uint32_t a;
    asm("{ .reg .u64 t; cvta.to.shared.u64 t, %1; cvt.u32.u64 %0, t; }" : "=r"(a) : "l"(p));
    return a;
}
__device__ __forceinline__ void mma16816(float* d, const uint32_t* a, const uint32_t* b) {
    asm volatile(
        "mma.sync.aligned.m16n8k16.row.col.f32.bf16.bf16.f32 "
        "{%0,%1,%2,%3}, {%4,%5,%6,%7}, {%8,%9}, {%0,%1,%2,%3};"
        : "+f"(d[0]), "+f"(d[1]), "+f"(d[2]), "+f"(d[3])
        : "r"(a[0]), "r"(a[1]), "r"(a[2]), "r"(a[3]), "r"(b[0]), "r"(b[1]));
}
__device__ __forceinline__ void ldsm4(uint32_t* r, uint32_t addr) {
    asm volatile("ldmatrix.sync.aligned.m8n8.x4.shared.b16 {%0,%1,%2,%3}, [%4];"
        : "=r"(r[0]), "=r"(r[1]), "=r"(r[2]), "=r"(r[3]) : "r"(addr));
}
__device__ __forceinline__ void cp16(uint32_t dst, const void* src) {
    asm volatile("cp.async.cg.shared.global [%0], [%1], 16;" :: "r"(dst), "l"(src));
}
#define CP_COMMIT() asm volatile("cp.async.commit_group;" ::: "memory")
#define CP_WAIT0()  asm volatile("cp.async.wait_group 0;" ::: "memory")

// ---------------- kernel 0a: constant head bias ----------------
__global__ void k_setup(const float* __restrict__ Ws1, const float* __restrict__ bs1,
                        const float* __restrict__ vn) {
    int h = blockIdx.x * (blockDim.x >> 5) + (threadIdx.x >> 5);
    int l = threadIdx.x & 31;
    if (h >= HHID) return;
    const float* row = Ws1 + (size_t)h * 512 + 256;
    float s = 0.f;
#pragma unroll
    for (int d = l; d < 256; d += 32) s += row[d] * vn[d];
#pragma unroll
    for (int off = 16; off; off >>= 1) s += __shfl_xor_sync(0xffffffffu, s, off);
    if (l == 0) g_cvec[h] = s + bs1[h];
}

// ---------------- kernel 0b: weights -> bf16 hi/lo, zero outputs ----------------
__global__ void k_prep(const float* __restrict__ Wa, const float* __restrict__ Ws1,
                       float* __restrict__ out_u) {
    int idx = blockIdx.x * blockDim.x + threadIdx.x;
    if (idx < DU * DMODEL) {
        float v = Wa[idx];
        __nv_bfloat16 hi = __float2bfloat16(v);
        __nv_bfloat16 lo = __float2bfloat16(v - __bfloat162float(hi));
        g_Wa_hi[idx] = hi;
        g_Wa_lo[idx] = lo;
    }
    if (idx < HHID * DMODEL) {
        int h = idx >> 8, d = idx & 255;
        float v = Ws1[h * 512 + d];
        __nv_bfloat16 hi = __float2bfloat16(v);
        __nv_bfloat16 lo = __float2bfloat16(v - __bfloat162float(hi));
        g_W1_hi[idx] = hi;
        g_W1_lo[idx] = lo;
    }
    if (idx < BATCH * DU) out_u[idx] = 0.f;
    if (idx < BATCH) g_count[idx] = 0;
    if (idx == 0) g_tile = 0;
}

// ---------------- kernel 1a: embedding + trig -> bf16 hi/lo ----------------
__global__ __launch_bounds__(256) void k_emb(
    const int* __restrict__ q_seq, const int* __restrict__ r_seq,
    const float* __restrict__ t_seq,
    const float* __restrict__ q_tab, const float* __restrict__ r_tab)
{
    __shared__ int sq[16], sr[16];
    __shared__ float st[16];
    const int tid = threadIdx.x;
    const int tok0 = blockIdx.x * 16;
    if (tid < 16) {
        sq[tid] = q_seq[tok0 + tid];
        sr[tid] = r_seq[tok0 + tid];
        st[tid] = t_seq[tok0 + tid];
    }
    __syncthreads();
    const int d = tid;
    const float ddf  = (float)(d & 127);
    const float freq = expf(ddf * (-9.2103403719761836f / 128.f));
    const bool is_sin = d < 128;
    __nv_bfloat16* ghi = g_hev_hi + (size_t)tok0 * 256 + d;
    __nv_bfloat16* glo = g_hev_lo + (size_t)tok0 * 256 + d;
#pragma unroll 4
    for (int t = 0; t < 16; ++t) {
        float arg = st[t] * freq;
        float tv  = is_sin ? sinf(arg) : cosf(arg);
        float val = q_tab[(size_t)sq[t] * 256 + d] + r_tab[sr[t] * 256 + d] + tv;
        __nv_bfloat16 hb = __float2bfloat16(val);
        ghi[(size_t)t * 256] = hb;
        glo[(size_t)t * 256] = __float2bfloat16(val - __bfloat162float(hb));
    }
}

// ---------------- kernel 1b: HMMA logits + compaction (512 thr, 16 warps) ----------------
// warp grid 4M x 4N; warp tile 32h x 32tok.
// smem: sW[2][128][528B]@0, sH[2][128][272B]@135168, slog[4][128]@204800, stile@206848
#define LW_OFF   0
#define LW_TERM  67584
#define LH_OFF   135168
#define LH_TERM  34816
#define LSLOG    204800
#define LSTILE   206848
#define SMEM_LG  206976

__global__ __launch_bounds__(512, 1) void k_logits_mma(
    const float* __restrict__ mask, const float* __restrict__ Ws2,
    const float* __restrict__ bs2, float* __restrict__ outA)
{
    extern __shared__ char smem[];
    const uint32_t sb = smem_u32(smem);
    const int tid  = threadIdx.x;
    const int wid  = tid >> 5;
    const int lane = tid & 31;
    const int gid  = lane >> 2;
    const int warpM = wid >> 2;       // 0..3 -> 32-h groups
    const int warpN = wid & 3;        // 0..3 -> 32-token groups

    float* slog  = (float*)(smem + LSLOG);
    int*   stile = (int*)(smem + LSTILE);

    // stage Ws1a hi/lo once per block
    for (int i = tid; i < 8192; i += 512) {
        int term = i >> 12;
        int r = (i >> 5) & 127;
        int c = i & 31;
        const __nv_bfloat16* src = term ? g_W1_lo : g_W1_hi;
        uint4 v = ((const uint4*)(src + ((size_t)r << 8)))[c];
        *(uint4*)(smem + LW_OFF + term * LW_TERM + r * 528 + c * 16) = v;
    }

    // per-thread epilogue constants (2 m-tiles of 16 h)
    float wc[2][2], cv[2][2];
#pragma unroll
    for (int m = 0; m < 2; ++m) {
        int h0 = warpM * 32 + m * 16 + gid;
        wc[m][0] = Ws2[h0];     wc[m][1] = Ws2[h0 + 8];
        cv[m][0] = g_cvec[h0];  cv[m][1] = g_cvec[h0 + 8];
    }
    const float b2v = bs2[0];

    // A-staging ids: 512 threads cover 2 terms x 128 rows x 2 halves (8 uint4 each)
    const int st_term = (tid >> 8) & 1;
    const int st_row  = (tid >> 1) & 127;
    const int st_half = tid & 1;

    const uint32_t w_ld = sb + LW_OFF + (uint32_t)((lane & 15) * 528 + (lane >> 4) * 16);
    const uint32_t h_ld = sb + LH_OFF +
        (uint32_t)((warpN * 32 + (lane & 15)) * 272 + (lane >> 4) * 16);

    if (tid == 0) *stile = atomicAdd(&g_tile, 1);
    __syncthreads();
    int tile = *stile;

    uint4 RA[8];
    if (tile < LTILE) {
        const uint4* p = (const uint4*)((st_term ? g_hev_lo : g_hev_hi)
                        + ((size_t)(tile * LTOK + st_row) << 8) + st_half * 64);
#pragma unroll
        for (int c = 0; c < 8; ++c) RA[c] = p[c];
    }

    while (tile < LTILE) {
        const int tok0 = tile * LTOK;
        const int b    = tok0 >> 11;

        // STS kh0
        {
            char* dst = smem + LH_OFF + st_term * LH_TERM + st_row * 272 + st_half * 128;
#pragma unroll
            for (int c = 0; c < 8; ++c) *(uint4*)(dst + c * 16) = RA[c];
        }
        __syncthreads();

        // LDG kh1 (overlaps GEMM kh0)
        {
            const uint4* p = (const uint4*)((st_term ? g_hev_lo : g_hev_hi)
                            + ((size_t)(tok0 + st_row) << 8) + 128 + st_half * 64);
#pragma unroll
            for (int c = 0; c < 8; ++c) RA[c] = p[c];
        }

        float C[2][4][4];
#pragma unroll
        for (int m = 0; m < 2; ++m)
#pragma unroll
            for (int n = 0; n < 4; ++n)
#pragma unroll
                for (int k = 0; k < 4; ++k) C[m][n][k] = 0.f;

        // ---- GEMM kh0 ----
#pragma unroll
        for (int ks = 0; ks < 8; ++ks) {
            uint32_t ah[2][4], al[2][4], bh[4][2], bl[4][2], tmp[4];
#pragma unroll
            for (int m = 0; m < 2; ++m) {
                uint32_t ro = (uint32_t)((warpM * 32 + m * 16) * 528 + ks * 32);
                ldsm4(ah[m], w_ld + ro);
                ldsm4(al[m], w_ld + LW_TERM + ro);
            }
#pragma unroll
            for (int nc = 0; nc < 2; ++nc) {
                uint32_t no = (uint32_t)(nc * 16 * 272 + ks * 32);
                ldsm4(tmp, h_ld + no);
                bh[2*nc][0] = tmp[0]; bh[2*nc+1][0] = tmp[1];
                bh[2*nc][1] = tmp[2]; bh[2*nc+1][1] = tmp[3];
                ldsm4(tmp, h_ld + LH_TERM + no);
                bl[2*nc][0] = tmp[0]; bl[2*nc+1][0] = tmp[1];
                bl[2*nc][1] = tmp[2]; bl[2*nc+1][1] = tmp[3];
            }
#pragma unroll
            for (int m = 0; m < 2; ++m)
#pragma unroll
                for (int n = 0; n < 4; ++n) mma16816(C[m][n], ah[m], bh[n]);
#pragma unroll
            for (int m = 0; m < 2; ++m)
#pragma unroll
                for (int n = 0; n < 4; ++n) mma16816(C[m][n], ah[m], bl[n]);
#pragma unroll
            for (int m = 0; m < 2; ++m)
#pragma unroll
                for (int n = 0; n < 4; ++n) mma16816(C[m][n], al[m], bh[n]);
        }
        __syncthreads();

        // STS kh1
        {
            char* dst = smem + LH_OFF + st_term * LH_TERM + st_row * 272 + st_half * 128;
#pragma unroll
            for (int c = 0; c < 8; ++c) *(uint4*)(dst + c * 16) = RA[c];
        }
        if (tid == 0) *stile = atomicAdd(&g_tile, 1);
        __syncthreads();

        // ---- GEMM kh1 ----
#pragma unroll
        for (int ks = 0; ks < 8; ++ks) {
            uint32_t ah[2][4], al[2][4], bh[4][2], bl[4][2], tmp[4];
#pragma unroll
            for (int m = 0; m < 2; ++m) {
                uint32_t ro = (uint32_t)((warpM * 32 + m * 16) * 528 + (8 + ks) * 32);
                ldsm4(ah[m], w_ld + ro);
                ldsm4(al[m], w_ld + LW_TERM + ro);
            }
#pragma unroll
            for (int nc = 0; nc < 2; ++nc) {
                uint32_t no = (uint32_t)(nc * 16 * 272 + ks * 32);
                ldsm4(tmp, h_ld + no);
                bh[2*nc][0] = tmp[0]; bh[2*nc+1][0] = tmp[1];
                bh[2*nc][1] = tmp[2]; bh[2*nc+1][1] = tmp[3];
                ldsm4(tmp, h_ld + LH_TERM + no);
                bl[2*nc][0] = tmp[0]; bl[2*nc+1][0] = tmp[1];
                bl[2*nc][1] = tmp[2]; bl[2*nc+1][1] = tmp[3];
            }
#pragma unroll
            for (int m = 0; m < 2; ++m)
#pragma unroll
                for (int n = 0; n < 4; ++n) mma16816(C[m][n], ah[m], bh[n]);
#pragma unroll
            for (int m = 0; m < 2; ++m)
#pragma unroll
                for (int n = 0; n < 4; ++n) mma16816(C[m][n], ah[m], bl[n]);
#pragma unroll
            for (int m = 0; m < 2; ++m)
#pragma unroll
                for (int n = 0; n < 4; ++n) mma16816(C[m][n], al[m], bh[n]);
        }

        const int nt = *stile;
        // LDG next tile kh0 (overlaps epilogue)
        if (nt < LTILE) {
            const uint4* p = (const uint4*)((st_term ? g_hev_lo : g_hev_hi)
                            + ((size_t)(nt * LTOK + st_row) << 8) + st_half * 64);
#pragma unroll
            for (int c = 0; c < 8; ++c) RA[c] = p[c];
        }

        // ---- epilogue: hdn -> ws2-weighted token partials ----
        {
            float tsum[4][2];
#pragma unroll
            for (int n = 0; n < 4; ++n) { tsum[n][0] = 0.f; tsum[n][1] = 0.f; }
#pragma unroll
            for (int m = 0; m < 2; ++m)
#pragma unroll
                for (int n = 0; n < 4; ++n) {
                    tsum[n][0] += wc[m][0] * lrelu(C[m][n][0] + cv[m][0])
                                + wc[m][1] * lrelu(C[m][n][2] + cv[m][1]);
                    tsum[n][1] += wc[m][0] * lrelu(C[m][n][1] + cv[m][0])
                                + wc[m][1] * lrelu(C[m][n][3] + cv[m][1]);
                }
#pragma unroll
            for (int n = 0; n < 4; ++n)
#pragma unroll
                for (int k2 = 0; k2 < 2; ++k2) {
                    float v = tsum[n][k2];
                    v += __shfl_xor_sync(0xffffffffu, v, 4);
                    v += __shfl_xor_sync(0xffffffffu, v, 8);
                    v += __shfl_xor_sync(0xffffffffu, v, 16);
                    tsum[n][k2] = v;
                }
            if (lane < 4) {
#pragma unroll
                for (int n = 0; n < 4; ++n) {
                    int t = warpN * 32 + n * 8 + 2 * lane;
                    slog[warpM * 128 + t]     = tsum[n][0];
                    slog[warpM * 128 + t + 1] = tsum[n][1];
                }
            }
        }
        __syncthreads();

        // ---- sigmoid + compaction (4 warps) ----
        if (tid < 128) {
            float logit = slog[tid] + slog[128 + tid] + slog[256 + tid]
                        + slog[384 + tid] + b2v;
            float a = mask[tok0 + tid] / (1.f + expf(-logit * 100.f));
            outA[tok0 + tid]   = a;
            g_aval[tok0 + tid] = a;
            bool act = a > 1e-10f;
            unsigned mb = __ballot_sync(0xffffffffu, act);
            int cntw = __popc(mb);
            int base = 0;
            if (lane == 0 && cntw) base = atomicAdd(&g_count[b], cntw);
            base = __shfl_sync(0xffffffffu, base, 0);
            if (act) {
                int slot = base + __popc(mb & ((1u << lane) - 1u));
                g_active[b * LSEQ + slot] = (tok0 & (LSEQ - 1)) + tid;
            }
        }
        tile = nt;
        __syncthreads();
    }
}

// ---------------- kernel 2: HMMA aggregator (512 thr, 16 warps, 4 batches/block) ----------------
// warp grid 4M x 4N; warp tile 16tok x 32col.
#define KA_B_OFF   0
#define KA_A_OFF   135168
#define KA_ABUF    34816
#define KA_ATERM   17408
#define KA_SA_OFF  204800
#define KA_STOK_OFF 205312
#define SMEM_AGG   205824

__global__ __launch_bounds__(512, 1) void k_agg_p(const float* __restrict__ ba,
                                                  float* __restrict__ out_u)
{
    extern __shared__ char smem[];
    const uint32_t sb = smem_u32(smem);
    const int tid  = threadIdx.x;
    const int wid  = tid >> 5;
    const int lane = tid & 31;
    const int gid  = lane >> 2;
    const int colbase = blockIdx.x * 128;
    const int warpM = wid >> 2;     // 0..3 -> 16-token groups
    const int warpN = wid & 3;      // 0..3 -> 32-col groups

    float* sa   = (float*)(smem + KA_SA_OFF);
    int*   stok = (int*)(smem + KA_STOK_OFF);

    // stage B (Wa slice hi+lo) once for all 4 batches
    for (int i = tid; i < 8192; i += 512) {
        int term = i >> 12;
        int r = (i >> 5) & 127;
        int c = i & 31;
        const __nv_bfloat16* src = term ? g_Wa_lo : g_Wa_hi;
        uint4 v = ((const uint4*)(src + ((size_t)(colbase + r) << 8)))[c];
        *(uint4*)(smem + KA_B_OFF + term * 67584 + r * 528 + c * 16) = v;
    }

    float ban0[4], ban1[4];
#pragma unroll
    for (int n = 0; n < 4; ++n) {
        int c0 = colbase + warpN * 32 + n * 8 + 2 * (lane & 3);
        ban0[n] = ba[c0];
        ban1[n] = ba[c0 + 1];
    }

    const uint32_t a_ld_base = sb + KA_A_OFF
        + (uint32_t)((lane & 15) * 272 + (lane >> 4) * 16);
    const uint32_t b_ld_base = sb + KA_B_OFF
        + (uint32_t)((warpN * 32 + (lane & 15)) * 528 + (lane >> 4) * 16);

    for (int bi = 0; bi < 4; ++bi) {
        const int b = blockIdx.y * 4 + bi;
        const int cnt = g_count[b];
        const int ntile = (cnt + 63) >> 6;

        __syncthreads();   // protect stok/sa reuse across batches (and after B stage)

        float colacc[4][2];
#pragma unroll
        for (int n = 0; n < 4; ++n) { colacc[n][0] = 0.f; colacc[n][1] = 0.f; }

        if (tid < 64 && ntile > 0) {
            int tok = (tid < cnt) ? g_active[(b << 11) + tid] : 0;
            stok[tid] = tok;
            sa[tid]   = (tid < cnt) ? g_aval[(b << 11) + tok] : 0.f;
        }
        __syncthreads();

        if (ntile > 0) {
#pragma unroll
            for (int i = 0; i < 4; ++i) {
                int idx = tid + i * 512;
                int term = idx >> 10;
                int row  = (idx >> 4) & 63;
                int c    = idx & 15;
                const __nv_bfloat16* src = term ? g_hev_lo : g_hev_hi;
                cp16(sb + KA_A_OFF + (uint32_t)(term * KA_ATERM + row * 272 + c * 16),
                     src + (((size_t)(b << 11) + stok[row]) << 8) + (c << 3));
            }
            CP_COMMIT();
        }

        int cur = 0;
        for (int t = 0; t < ntile; ++t, cur ^= 1) {
            const int nxt = cur ^ 1;
            if (tid < 64 && t + 1 < ntile) {
                int slot = ((t + 1) << 6) + tid;
                int tok = (slot < cnt) ? g_active[(b << 11) + slot] : 0;
                stok[nxt * 64 + tid] = tok;
                sa[nxt * 64 + tid]   = (slot < cnt) ? g_aval[(b << 11) + tok] : 0.f;
            }
            CP_WAIT0();
            __syncthreads();

#pragma unroll
            for (int i = 0; i < 4; ++i) {
                int idx = tid + i * 512;
                int term = idx >> 10;
                int row  = (idx >> 4) & 63;
                int c    = idx & 15;
                const __nv_bfloat16* src = term ? g_hev_lo : g_hev_hi;
                cp16(sb + KA_A_OFF + KA_ABUF
                         + (uint32_t)(term * KA_ATERM + row * 272 + c * 16),
                     src + (((size_t)(b << 11) + stok[cur * 64 + row]) << 8) + 128 + (c << 3));
            }
            CP_COMMIT();

            float C[4][4];
#pragma unroll
            for (int n = 0; n < 4; ++n)
#pragma unroll
                for (int k = 0; k < 4; ++k) C[n][k] = 0.f;

#pragma unroll
            for (int ks = 0; ks < 8; ++ks) {
                uint32_t ah[4], al[4], bh[4][2], bl[4][2], tmp[4];
                {
                    uint32_t ro = (uint32_t)((warpM * 16) * 272 + ks * 32);
                    ldsm4(ah, a_ld_base + ro);
                    ldsm4(al, a_ld_base + KA_ATERM + ro);
                }
#pragma unroll
                for (int nc = 0; nc < 2; ++nc) {
                    uint32_t no = (uint32_t)(nc * 16 * 528 + ks * 32);
                    ldsm4(tmp, b_ld_base + no);
                    bh[2*nc][0] = tmp[0]; bh[2*nc+1][0] = tmp[1];
                    bh[2*nc][1] = tmp[2]; bh[2*nc+1][1] = tmp[3];
                    ldsm4(tmp, b_ld_base + 67584 + no);
                    bl[2*nc][0] = tmp[0]; bl[2*nc+1][0] = tmp[1];
                    bl[2*nc][1] = tmp[2]; bl[2*nc+1][1] = tmp[3];
                }
#pragma unroll
                for (int n = 0; n < 4; ++n) mma16816(C[n], ah, bh[n]);
#pragma unroll
                for (int n = 0; n < 4; ++n) mma16816(C[n], ah, bl[n]);
#pragma unroll
                for (int n = 0; n < 4; ++n) mma16816(C[n], al, bh[n]);
            }

            CP_WAIT0();
            __syncthreads();

            if (t + 1 < ntile) {
#pragma unroll
                for (int i = 0; i < 4; ++i) {
                    int idx = tid + i * 512;
                    int term = idx >> 10;
                    int row  = (idx >> 4) & 63;
                    int c    = idx & 15;
                    const __nv_bfloat16* src = term ? g_hev_lo : g_hev_hi;
                    cp16(sb + KA_A_OFF + (uint32_t)(term * KA_ATERM + row * 272 + c * 16),
                         src + (((size_t)(b << 11) + stok[nxt * 64 + row]) << 8) + (c << 3));
                }
                CP_COMMIT();
            }

#pragma unroll
            for (int ks = 0; ks < 8; ++ks) {
                uint32_t ah[4], al[4], bh[4][2], bl[4][2], tmp[4];
                {
                    uint32_t ro = (uint32_t)((warpM * 16) * 272 + ks * 32);
                    ldsm4(ah, a_ld_base + KA_ABUF + ro);
                    ldsm4(al, a_ld_base + KA_ABUF + KA_ATERM + ro);
                }
#pragma unroll
                for (int nc = 0; nc < 2; ++nc) {
                    uint32_t no = (uint32_t)(nc * 16 * 528 + 256 + ks * 32);
                    ldsm4(tmp, b_ld_base + no);
                    bh[2*nc][0] = tmp[0]; bh[2*nc+1][0] = tmp[1];
                    bh[2*nc][1] = tmp[2]; bh[2*nc+1][1] = tmp[3];
                    ldsm4(tmp, b_ld_base + 67584 + no);
                    bl[2*nc][0] = tmp[0]; bl[2*nc+1][0] = tmp[1];
                    bl[2*nc][1] = tmp[2]; bl[2*nc+1][1] = tmp[3];
                }
#pragma unroll
                for (int n = 0; n < 4; ++n) mma16816(C[n], ah, bh[n]);
#pragma unroll
                for (int n = 0; n < 4; ++n) mma16816(C[n], ah, bl[n]);
#pragma unroll
                for (int n = 0; n < 4; ++n) mma16816(C[n], al, bh[n]);
            }

            // epilogue: a-weighted lrelu accumulate
            {
                float a0 = sa[cur * 64 + warpM * 16 + gid];
                float a1 = sa[cur * 64 + warpM * 16 + gid + 8];
#pragma unroll
                for (int n = 0; n < 4; ++n) {
                    colacc[n][0] += a0 * lrelu(C[n][0] + ban0[n])
                                  + a1 * lrelu(C[n][2] + ban0[n]);
                    colacc[n][1] += a0 * lrelu(C[n][1] + ban1[n])
                                  + a1 * lrelu(C[n][3] + ban1[n]);
                }
            }
        }

#pragma unroll
        for (int n = 0; n < 4; ++n)
#pragma unroll
            for (int j = 0; j < 2; ++j) {
                float v = colacc[n][j];
                v += __shfl_xor_sync(0xffffffffu, v, 4);
                v += __shfl_xor_sync(0xffffffffu, v, 8);
                v += __shfl_xor_sync(0xffffffffu, v, 16);
                colacc[n][j] = v;
            }
        if (lane < 4) {
#pragma unroll
            for (int n = 0; n < 4; ++n) {
                int c0 = colbase + warpN * 32 + n * 8 + 2 * lane;
                atomicAdd(&out_u[b * DU + c0],     colacc[n][0]);
                atomicAdd(&out_u[b * DU + c0 + 1], colacc[n][1]);
            }
        }
    }
}

// ---------------- launch ----------------
extern "C" void kernel_launch(void* const* d_in, const int* in_sizes, int n_in,
                              void* d_out, int out_size) {
    const int*   q_seq = (const int*)d_in[0];
    const int*   r_seq = (const int*)d_in[1];
    const float* t_seq = (const float*)d_in[2];
    const float* mask  = (const float*)d_in[3];
    const float* q_tab = (const float*)d_in[4];
    const float* r_tab = (const float*)d_in[5];
    const float* vn    = (const float*)d_in[6];
    const float* Ws1   = (const float*)d_in[7];
    const float* bs1   = (const float*)d_in[8];
    const float* Ws2   = (const float*)d_in[9];
    const float* bs2   = (const float*)d_in[10];
    const float* Wa    = (const float*)d_in[11];
    const float* ba    = (const float*)d_in[12];

    float* out_u = (float*)d_out;            // (64, 1024)
    float* outA  = out_u + BATCH * DU;       // (64, 2048)

    k_setup<<<4, 1024>>>(Ws1, bs1, vn);
    k_prep<<<(DU * DMODEL + 255) / 256, 256>>>(Wa, Ws1, out_u);

    k_emb<<<NTOK / 16, 256>>>(q_seq, r_seq, t_seq, q_tab, r_tab);

    cudaFuncSetAttribute(k_logits_mma, cudaFuncAttributeMaxDynamicSharedMemorySize, SMEM_LG);
    k_logits_mma<<<148, 512, SMEM_LG>>>(mask, Ws2, bs2, outA);

    cudaFuncSetAttribute(k_agg_p, cudaFuncAttributeMaxDynamicSharedMemorySize, SMEM_AGG);
    k_agg_p<<<dim3(8, 16), 512, SMEM_AGG>>>(ba, out_u);
}

// round 10
// speedup vs baseline: 1.0499x; 1.0317x over previous
#include <cuda_runtime.h>
#include <cuda_bf16.h>
#include <math.h>
#include <stdint.h>

typedef unsigned long long ull;

#define BATCH 64
#define LSEQ  2048
#define DMODEL 256
#define DU 1024
#define HHID 128
#define NTOK (BATCH*LSEQ)
#define LTOK 64
#define NT2 (NTOK/LTOK)   // 2048

// ---------------- device scratch ----------------
__device__ __nv_bfloat16 g_hev_hi[(size_t)NTOK * DMODEL];
__device__ __nv_bfloat16 g_hev_lo[(size_t)NTOK * DMODEL];
__device__ __nv_bfloat16 g_Wa_hi[DU * DMODEL];
__device__ __nv_bfloat16 g_Wa_lo[DU * DMODEL];
__device__ __nv_bfloat16 g_W1_hi[HHID * DMODEL];
__device__ __nv_bfloat16 g_W1_lo[HHID * DMODEL];
__device__ float g_cvec[HHID];
__device__ float g_aval[NTOK];
__device__ int   g_active[NTOK];
__device__ int   g_count[BATCH];
__device__ int   g_tile;

// ---------------- helpers ----------------
__device__ __forceinline__ float lrelu(float x) { return x > 0.f ? x : 0.2f * x; }

__device__ __forceinline__ uint32_t smem_u32(const void* p) {
    uint32_t a;
    asm("{ .reg .u64 t; cvta.to.shared.u64 t, %1; cvt.u32.u64 %0, t; }" : "=r"(a) : "l"(p));
    return a;
}
__device__ __forceinline__ void mma16816(float* d, const uint32_t* a, const uint32_t* b) {
    asm volatile(
        "mma.sync.aligned.m16n8k16.row.col.f32.bf16.bf16.f32 "
        "{%0,%1,%2,%3}, {%4,%5,%6,%7}, {%8,%9}, {%0,%1,%2,%3};"
        : "+f"(d[0]), "+f"(d[1]), "+f"(d[2]), "+f"(d[3])
        : "r"(a[0]), "r"(a[1]), "r"(a[2]), "r"(a[3]), "r"(b[0]), "r"(b[1]));
}
__device__ __forceinline__ void ldsm4(uint32_t* r, uint32_t addr) {
    asm volatile("ldmatrix.sync.aligned.m8n8.x4.shared.b16 {%0,%1,%2,%3}, [%4];"
        : "=r"(r[0]), "=r"(r[1]), "=r"(r[2]), "=r"(r[3]) : "r"(addr));
}
__device__ __forceinline__ void cp16(uint32_t dst, const void* src) {
    asm volatile("cp.async.cg.shared.global [%0], [%1], 16;" :: "r"(dst), "l"(src));
}
#define CP_COMMIT() asm volatile("cp.async.commit_group;" ::: "memory")
#define CP_WAIT0()  asm volatile("cp.async.wait_group 0;" ::: "memory")
#define CP_WAIT1()  asm volatile("cp.async.wait_group 1;" ::: "memory")

// ---------------- kernel 0a: constant head bias ----------------
__global__ void k_setup(const float* __restrict__ Ws1, const float* __restrict__ bs1,
                        const float* __restrict__ vn) {
    int h = blockIdx.x * (blockDim.x >> 5) + (threadIdx.x >> 5);
    int l = threadIdx.x & 31;
    if (h >= HHID) return;
    const float* row = Ws1 + (size_t)h * 512 + 256;
    float s = 0.f;
#pragma unroll
    for (int d = l; d < 256; d += 32) s += row[d] * vn[d];
#pragma unroll
    for (int off = 16; off; off >>= 1) s += __shfl_xor_sync(0xffffffffu, s, off);
    if (l == 0) g_cvec[h] = s + bs1[h];
}

// ---------------- kernel 0b: weights -> bf16 hi/lo, zero outputs ----------------
__global__ void k_prep(const float* __restrict__ Wa, const float* __restrict__ Ws1,
                       float* __restrict__ out_u) {
    int idx = blockIdx.x * blockDim.x + threadIdx.x;
    if (idx < DU * DMODEL) {
        float v = Wa[idx];
        __nv_bfloat16 hi = __float2bfloat16(v);
        __nv_bfloat16 lo = __float2bfloat16(v - __bfloat162float(hi));
        g_Wa_hi[idx] = hi;
        g_Wa_lo[idx] = lo;
    }
    if (idx < HHID * DMODEL) {
        int h = idx >> 8, d = idx & 255;
        float v = Ws1[h * 512 + d];
        __nv_bfloat16 hi = __float2bfloat16(v);
        __nv_bfloat16 lo = __float2bfloat16(v - __bfloat162float(hi));
        g_W1_hi[idx] = hi;
        g_W1_lo[idx] = lo;
    }
    if (idx < BATCH * DU) out_u[idx] = 0.f;
    if (idx < BATCH) g_count[idx] = 0;
    if (idx == 0) g_tile = 0;
}

// ---------------- kernel 1a: embedding + trig -> bf16 hi/lo ----------------
__global__ __launch_bounds__(256) void k_emb(
    const int* __restrict__ q_seq, const int* __restrict__ r_seq,
    const float* __restrict__ t_seq,
    const float* __restrict__ q_tab, const float* __restrict__ r_tab)
{
    __shared__ int sq[16], sr[16];
    __shared__ float st[16];
    const int tid = threadIdx.x;
    const int tok0 = blockIdx.x * 16;
    if (tid < 16) {
        sq[tid] = q_seq[tok0 + tid];
        sr[tid] = r_seq[tok0 + tid];
        st[tid] = t_seq[tok0 + tid];
    }
    __syncthreads();
    const int d = tid;
    const float ddf  = (float)(d & 127);
    const float freq = expf(ddf * (-9.2103403719761836f / 128.f));
    const bool is_sin = d < 128;
    __nv_bfloat16* ghi = g_hev_hi + (size_t)tok0 * 256 + d;
    __nv_bfloat16* glo = g_hev_lo + (size_t)tok0 * 256 + d;
#pragma unroll 4
    for (int t = 0; t < 16; ++t) {
        float arg = st[t] * freq;
        float tv  = is_sin ? sinf(arg) : cosf(arg);
        float val = q_tab[(size_t)sq[t] * 256 + d] + r_tab[sr[t] * 256 + d] + tv;
        __nv_bfloat16 hb = __float2bfloat16(val);
        ghi[(size_t)t * 256] = hb;
        glo[(size_t)t * 256] = __float2bfloat16(val - __bfloat162float(hb));
    }
}

// ---------------- kernel 1b: pipelined HMMA logits (512 thr, 64-token tiles) ----------------
// warp grid 4M x 4N; warp tile 32h x 16tok. cp.async double-buffered A halves.
// smem: sW[2][128][528B]@0 (135168), sH[2 bufs][2 terms][64][272B]@135168 (69632),
//       slog[4][64]@204800 (1024), stile@205824
#define LW_OFF   0
#define LW_TERM  67584
#define LH_OFF   135168
#define LH_BUF   34816
#define LH_TERM  17408
#define LSLOG    204800
#define LSTILE   205824
#define SMEM_LG  205952

__global__ __launch_bounds__(512, 1) void k_logits_mma(
    const float* __restrict__ mask, const float* __restrict__ Ws2,
    const float* __restrict__ bs2, float* __restrict__ outA)
{
    extern __shared__ char smem[];
    const uint32_t sb = smem_u32(smem);
    const int tid  = threadIdx.x;
    const int wid  = tid >> 5;
    const int lane = tid & 31;
    const int gid  = lane >> 2;
    const int warpM = wid >> 2;       // 0..3 -> 32-h groups
    const int warpN = wid & 3;        // 0..3 -> 16-token groups

    float* slog  = (float*)(smem + LSLOG);
    int*   stile = (int*)(smem + LSTILE);

    // stage Ws1a hi/lo once per block
    for (int i = tid; i < 8192; i += 512) {
        int term = i >> 12;
        int r = (i >> 5) & 127;
        int c = i & 31;
        const __nv_bfloat16* src = term ? g_W1_lo : g_W1_hi;
        uint4 v = ((const uint4*)(src + ((size_t)r << 8)))[c];
        *(uint4*)(smem + LW_OFF + term * LW_TERM + r * 528 + c * 16) = v;
    }

    // per-thread epilogue constants (2 m-tiles of 16 h)
    float wc[2][2], cv[2][2];
#pragma unroll
    for (int m = 0; m < 2; ++m) {
        int h0 = warpM * 32 + m * 16 + gid;
        wc[m][0] = Ws2[h0];     wc[m][1] = Ws2[h0 + 8];
        cv[m][0] = g_cvec[h0];  cv[m][1] = g_cvec[h0 + 8];
    }
    const float b2v = bs2[0];

    const uint32_t w_ld = sb + LW_OFF + (uint32_t)((lane & 15) * 528 + (lane >> 4) * 16);
    const uint32_t h_ld = sb + LH_OFF +
        (uint32_t)((warpN * 16 + (lane & 15)) * 272 + (lane >> 4) * 16);

    // cp.async staging lambda-ish (4 cp16 per thread per half)
    const int st_term = tid >> 10;        // always 0 for tid<512; recomputed per idx below

    if (tid == 0) *stile = atomicAdd(&g_tile, 1);
    __syncthreads();
    int tile = *stile;
    (void)st_term;

    // prologue: issue kh0 -> buf0
    if (tile < NT2) {
#pragma unroll
        for (int i = 0; i < 4; ++i) {
            int idx = tid + i * 512;
            int term = idx >> 10;
            int row  = (idx >> 4) & 63;
            int c    = idx & 15;
            const __nv_bfloat16* src = term ? g_hev_lo : g_hev_hi;
            cp16(sb + LH_OFF + (uint32_t)(term * LH_TERM + row * 272 + c * 16),
                 src + (((size_t)(tile * LTOK + row)) << 8) + (c << 3));
        }
        CP_COMMIT();
    }

    while (tile < NT2) {
        const int tok0 = tile * LTOK;
        const int b    = tok0 >> 11;

        // issue kh1 -> buf1
#pragma unroll
        for (int i = 0; i < 4; ++i) {
            int idx = tid + i * 512;
            int term = idx >> 10;
            int row  = (idx >> 4) & 63;
            int c    = idx & 15;
            const __nv_bfloat16* src = term ? g_hev_lo : g_hev_hi;
            cp16(sb + LH_OFF + LH_BUF + (uint32_t)(term * LH_TERM + row * 272 + c * 16),
                 src + (((size_t)(tok0 + row)) << 8) + 128 + (c << 3));
        }
        CP_COMMIT();
        if (tid == 0) *stile = atomicAdd(&g_tile, 1);

        CP_WAIT1();
        __syncthreads();        // buf0 (kh0) ready

        float C[2][2][4];
#pragma unroll
        for (int m = 0; m < 2; ++m)
#pragma unroll
            for (int n = 0; n < 2; ++n)
#pragma unroll
                for (int k = 0; k < 4; ++k) C[m][n][k] = 0.f;

        // ---- GEMM kh0 (buf0) ----
#pragma unroll
        for (int ks = 0; ks < 8; ++ks) {
            uint32_t ah[2][4], al[2][4], bh[2][2], bl[2][2], tmp[4];
#pragma unroll
            for (int m = 0; m < 2; ++m) {
                uint32_t ro = (uint32_t)((warpM * 32 + m * 16) * 528 + ks * 32);
                ldsm4(ah[m], w_ld + ro);
                ldsm4(al[m], w_ld + LW_TERM + ro);
            }
            {
                uint32_t no = (uint32_t)(ks * 32);
                ldsm4(tmp, h_ld + no);
                bh[0][0] = tmp[0]; bh[1][0] = tmp[1];
                bh[0][1] = tmp[2]; bh[1][1] = tmp[3];
                ldsm4(tmp, h_ld + LH_TERM + no);
                bl[0][0] = tmp[0]; bl[1][0] = tmp[1];
                bl[0][1] = tmp[2]; bl[1][1] = tmp[3];
            }
#pragma unroll
            for (int m = 0; m < 2; ++m)
#pragma unroll
                for (int n = 0; n < 2; ++n) mma16816(C[m][n], ah[m], bh[n]);
#pragma unroll
            for (int m = 0; m < 2; ++m)
#pragma unroll
                for (int n = 0; n < 2; ++n) mma16816(C[m][n], ah[m], bl[n]);
#pragma unroll
            for (int m = 0; m < 2; ++m)
#pragma unroll
                for (int n = 0; n < 2; ++n) mma16816(C[m][n], al[m], bh[n]);
        }
        __syncthreads();        // buf0 free

        const int nt = *stile;
        if (nt < NT2) {
            // issue next-tile kh0 -> buf0
#pragma unroll
            for (int i = 0; i < 4; ++i) {
                int idx = tid + i * 512;
                int term = idx >> 10;
                int row  = (idx >> 4) & 63;
                int c    = idx & 15;
                const __nv_bfloat16* src = term ? g_hev_lo : g_hev_hi;
                cp16(sb + LH_OFF + (uint32_t)(term * LH_TERM + row * 272 + c * 16),
                     src + (((size_t)(nt * LTOK + row)) << 8) + (c << 3));
            }
            CP_COMMIT();
            CP_WAIT1();
        } else {
            CP_WAIT0();
        }
        __syncthreads();        // buf1 (kh1) ready

        // ---- GEMM kh1 (buf1) ----
#pragma unroll
        for (int ks = 0; ks < 8; ++ks) {
            uint32_t ah[2][4], al[2][4], bh[2][2], bl[2][2], tmp[4];
#pragma unroll
            for (int m = 0; m < 2; ++m) {
                uint32_t ro = (uint32_t)((warpM * 32 + m * 16) * 528 + (8 + ks) * 32);
                ldsm4(ah[m], w_ld + ro);
                ldsm4(al[m], w_ld + LW_TERM + ro);
            }
            {
                uint32_t no = (uint32_t)(LH_BUF + ks * 32);
                ldsm4(tmp, h_ld + no);
                bh[0][0] = tmp[0]; bh[1][0] = tmp[1];
                bh[0][1] = tmp[2]; bh[1][1] = tmp[3];
                ldsm4(tmp, h_ld + LH_TERM + no);
                bl[0][0] = tmp[0]; bl[1][0] = tmp[1];
                bl[0][1] = tmp[2]; bl[1][1] = tmp[3];
            }
#pragma unroll
            for (int m = 0; m < 2; ++m)
#pragma unroll
                for (int n = 0; n < 2; ++n) mma16816(C[m][n], ah[m], bh[n]);
#pragma unroll
            for (int m = 0; m < 2; ++m)
#pragma unroll
                for (int n = 0; n < 2; ++n) mma16816(C[m][n], ah[m], bl[n]);
#pragma unroll
            for (int m = 0; m < 2; ++m)
#pragma unroll
                for (int n = 0; n < 2; ++n) mma16816(C[m][n], al[m], bh[n]);
        }

        // ---- epilogue: hdn -> ws2-weighted token partials ----
        {
            float tsum[2][2];
#pragma unroll
            for (int n = 0; n < 2; ++n) { tsum[n][0] = 0.f; tsum[n][1] = 0.f; }
#pragma unroll
            for (int m = 0; m < 2; ++m)
#pragma unroll
                for (int n = 0; n < 2; ++n) {
                    tsum[n][0] += wc[m][0] * lrelu(C[m][n][0] + cv[m][0])
                                + wc[m][1] * lrelu(C[m][n][2] + cv[m][1]);
                    tsum[n][1] += wc[m][0] * lrelu(C[m][n][1] + cv[m][0])
                                + wc[m][1] * lrelu(C[m][n][3] + cv[m][1]);
                }
#pragma unroll
            for (int n = 0; n < 2; ++n)
#pragma unroll
                for (int k2 = 0; k2 < 2; ++k2) {
                    float v = tsum[n][k2];
                    v += __shfl_xor_sync(0xffffffffu, v, 4);
                    v += __shfl_xor_sync(0xffffffffu, v, 8);
                    v += __shfl_xor_sync(0xffffffffu, v, 16);
                    tsum[n][k2] = v;
                }
            if (lane < 4) {
#pragma unroll
                for (int n = 0; n < 2; ++n) {
                    int t = warpN * 16 + n * 8 + 2 * lane;
                    slog[warpM * 64 + t]     = tsum[n][0];
                    slog[warpM * 64 + t + 1] = tsum[n][1];
                }
            }
        }
        __syncthreads();

        // ---- sigmoid + compaction (2 warps) ----
        if (tid < 64) {
            float logit = slog[tid] + slog[64 + tid] + slog[128 + tid]
                        + slog[192 + tid] + b2v;
            float a = mask[tok0 + tid] / (1.f + expf(-logit * 100.f));
            outA[tok0 + tid]   = a;
            g_aval[tok0 + tid] = a;
            bool act = a > 1e-10f;
            unsigned mb = __ballot_sync(0xffffffffu, act);
            int cntw = __popc(mb);
            int base = 0;
            if (lane == 0 && cntw) base = atomicAdd(&g_count[b], cntw);
            base = __shfl_sync(0xffffffffu, base, 0);
            if (act) {
                int slot = base + __popc(mb & ((1u << lane) - 1u));
                g_active[b * LSEQ + slot] = (tok0 & (LSEQ - 1)) + tid;
            }
        }
        tile = nt;
        __syncthreads();
    }
}

// ---------------- kernel 2: HMMA aggregator (512 thr, 16 warps, 4 batches/block) ----------------
#define KA_B_OFF   0
#define KA_A_OFF   135168
#define KA_ABUF    34816
#define KA_ATERM   17408
#define KA_SA_OFF  204800
#define KA_STOK_OFF 205312
#define SMEM_AGG   205824

__global__ __launch_bounds__(512, 1) void k_agg_p(const float* __restrict__ ba,
                                                  float* __restrict__ out_u)
{
    extern __shared__ char smem[];
    const uint32_t sb = smem_u32(smem);
    const int tid  = threadIdx.x;
    const int wid  = tid >> 5;
    const int lane = tid & 31;
    const int gid  = lane >> 2;
    const int colbase = blockIdx.x * 128;
    const int warpM = wid >> 2;
    const int warpN = wid & 3;

    float* sa   = (float*)(smem + KA_SA_OFF);
    int*   stok = (int*)(smem + KA_STOK_OFF);

    for (int i = tid; i < 8192; i += 512) {
        int term = i >> 12;
        int r = (i >> 5) & 127;
        int c = i & 31;
        const __nv_bfloat16* src = term ? g_Wa_lo : g_Wa_hi;
        uint4 v = ((const uint4*)(src + ((size_t)(colbase + r) << 8)))[c];
        *(uint4*)(smem + KA_B_OFF + term * 67584 + r * 528 + c * 16) = v;
    }

    float ban0[4], ban1[4];
#pragma unroll
    for (int n = 0; n < 4; ++n) {
        int c0 = colbase + warpN * 32 + n * 8 + 2 * (lane & 3);
        ban0[n] = ba[c0];
        ban1[n] = ba[c0 + 1];
    }

    const uint32_t a_ld_base = sb + KA_A_OFF
        + (uint32_t)((lane & 15) * 272 + (lane >> 4) * 16);
    const uint32_t b_ld_base = sb + KA_B_OFF
        + (uint32_t)((warpN * 32 + (lane & 15)) * 528 + (lane >> 4) * 16);

    for (int bi = 0; bi < 4; ++bi) {
        const int b = blockIdx.y * 4 + bi;
        const int cnt = g_count[b];
        const int ntile = (cnt + 63) >> 6;

        __syncthreads();

        float colacc[4][2];
#pragma unroll
        for (int n = 0; n < 4; ++n) { colacc[n][0] = 0.f; colacc[n][1] = 0.f; }

        if (tid < 64 && ntile > 0) {
            int tok = (tid < cnt) ? g_active[(b << 11) + tid] : 0;
            stok[tid] = tok;
            sa[tid]   = (tid < cnt) ? g_aval[(b << 11) + tok] : 0.f;
        }
        __syncthreads();

        if (ntile > 0) {
#pragma unroll
            for (int i = 0; i < 4; ++i) {
                int idx = tid + i * 512;
                int term = idx >> 10;
                int row  = (idx >> 4) & 63;
                int c    = idx & 15;
                const __nv_bfloat16* src = term ? g_hev_lo : g_hev_hi;
                cp16(sb + KA_A_OFF + (uint32_t)(term * KA_ATERM + row * 272 + c * 16),
                     src + (((size_t)(b << 11) + stok[row]) << 8) + (c << 3));
            }
            CP_COMMIT();
        }

        int cur = 0;
        for (int t = 0; t < ntile; ++t, cur ^= 1) {
            const int nxt = cur ^ 1;
            if (tid < 64 && t + 1 < ntile) {
                int slot = ((t + 1) << 6) + tid;
                int tok = (slot < cnt) ? g_active[(b << 11) + slot] : 0;
                stok[nxt * 64 + tid] = tok;
                sa[nxt * 64 + tid]   = (slot < cnt) ? g_aval[(b << 11) + tok] : 0.f;
            }
            CP_WAIT0();
            __syncthreads();

#pragma unroll
            for (int i = 0; i < 4; ++i) {
                int idx = tid + i * 512;
                int term = idx >> 10;
                int row  = (idx >> 4) & 63;
                int c    = idx & 15;
                const __nv_bfloat16* src = term ? g_hev_lo : g_hev_hi;
                cp16(sb + KA_A_OFF + KA_ABUF
                         + (uint32_t)(term * KA_ATERM + row * 272 + c * 16),
                     src + (((size_t)(b << 11) + stok[cur * 64 + row]) << 8) + 128 + (c << 3));
            }
            CP_COMMIT();

            float C[4][4];
#pragma unroll
            for (int n = 0; n < 4; ++n)
#pragma unroll
                for (int k = 0; k < 4; ++k) C[n][k] = 0.f;

#pragma unroll
            for (int ks = 0; ks < 8; ++ks) {
                uint32_t ah[4], al[4], bh[4][2], bl[4][2], tmp[4];
                {
                    uint32_t ro = (uint32_t)((warpM * 16) * 272 + ks * 32);
                    ldsm4(ah, a_ld_base + ro);
                    ldsm4(al, a_ld_base + KA_ATERM + ro);
                }
#pragma unroll
                for (int nc = 0; nc < 2; ++nc) {
                    uint32_t no = (uint32_t)(nc * 16 * 528 + ks * 32);
                    ldsm4(tmp, b_ld_base + no);
                    bh[2*nc][0] = tmp[0]; bh[2*nc+1][0] = tmp[1];
                    bh[2*nc][1] = tmp[2]; bh[2*nc+1][1] = tmp[3];
                    ldsm4(tmp, b_ld_base + 67584 + no);
                    bl[2*nc][0] = tmp[0]; bl[2*nc+1][0] = tmp[1];
                    bl[2*nc][1] = tmp[2]; bl[2*nc+1][1] = tmp[3];
                }
#pragma unroll
                for (int n = 0; n < 4; ++n) mma16816(C[n], ah, bh[n]);
#pragma unroll
                for (int n = 0; n < 4; ++n) mma16816(C[n], ah, bl[n]);
#pragma unroll
                for (int n = 0; n < 4; ++n) mma16816(C[n], al, bh[n]);
            }

            CP_WAIT0();
            __syncthreads();

            if (t + 1 < ntile) {
#pragma unroll
                for (int i = 0; i < 4; ++i) {
                    int idx = tid + i * 512;
                    int term = idx >> 10;
                    int row  = (idx >> 4) & 63;
                    int c    = idx & 15;
                    const __nv_bfloat16* src = term ? g_hev_lo : g_hev_hi;
                    cp16(sb + KA_A_OFF + (uint32_t)(term * KA_ATERM + row * 272 + c * 16),
                         src + (((size_t)(b << 11) + stok[nxt * 64 + row]) << 8) + (c << 3));
                }
                CP_COMMIT();
            }

#pragma unroll
            for (int ks = 0; ks < 8; ++ks) {
                uint32_t ah[4], al[4], bh[4][2], bl[4][2], tmp[4];
                {
                    uint32_t ro = (uint32_t)((warpM * 16) * 272 + ks * 32);
                    ldsm4(ah, a_ld_base + KA_ABUF + ro);
                    ldsm4(al, a_ld_base + KA_ABUF + KA_ATERM + ro);
                }
#pragma unroll
                for (int nc = 0; nc < 2; ++nc) {
                    uint32_t no = (uint32_t)(nc * 16 * 528 + 256 + ks * 32);
                    ldsm4(tmp, b_ld_base + no);
                    bh[2*nc][0] = tmp[0]; bh[2*nc+1][0] = tmp[1];
                    bh[2*nc][1] = tmp[2]; bh[2*nc+1][1] = tmp[3];
                    ldsm4(tmp, b_ld_base + 67584 + no);
                    bl[2*nc][0] = tmp[0]; bl[2*nc+1][0] = tmp[1];
                    bl[2*nc][1] = tmp[2]; bl[2*nc+1][1] = tmp[3];
                }
#pragma unroll
                for (int n = 0; n < 4; ++n) mma16816(C[n], ah, bh[n]);
#pragma unroll
                for (int n = 0; n < 4; ++n) mma16816(C[n], ah, bl[n]);
#pragma unroll
                for (int n = 0; n < 4; ++n) mma16816(C[n], al, bh[n]);
            }

            {
                float a0 = sa[cur * 64 + warpM * 16 + gid];
                float a1 = sa[cur * 64 + warpM * 16 + gid + 8];
#pragma unroll
                for (int n = 0; n < 4; ++n) {
                    colacc[n][0] += a0 * lrelu(C[n][0] + ban0[n])
                                  + a1 * lrelu(C[n][2] + ban0[n]);
                    colacc[n][1] += a0 * lrelu(C[n][1] + ban1[n])
                                  + a1 * lrelu(C[n][3] + ban1[n]);
                }
            }
        }

#pragma unroll
        for (int n = 0; n < 4; ++n)
#pragma unroll
            for (int j = 0; j < 2; ++j) {
                float v = colacc[n][j];
                v += __shfl_xor_sync(0xffffffffu, v, 4);
                v += __shfl_xor_sync(0xffffffffu, v, 8);
                v += __shfl_xor_sync(0xffffffffu, v, 16);
                colacc[n][j] = v;
            }
        if (lane < 4) {
#pragma unroll
            for (int n = 0; n < 4; ++n) {
                int c0 = colbase + warpN * 32 + n * 8 + 2 * lane;
                atomicAdd(&out_u[b * DU + c0],     colacc[n][0]);
                atomicAdd(&out_u[b * DU + c0 + 1], colacc[n][1]);
            }
        }
    }
}

// ---------------- launch ----------------
extern "C" void kernel_launch(void* const* d_in, const int* in_sizes, int n_in,
                              void* d_out, int out_size) {
    const int*   q_seq = (const int*)d_in[0];
    const int*   r_seq = (const int*)d_in[1];
    const float* t_seq = (const float*)d_in[2];
    const float* mask  = (const float*)d_in[3];
    const float* q_tab = (const float*)d_in[4];
    const float* r_tab = (const float*)d_in[5];
    const float* vn    = (const float*)d_in[6];
    const float* Ws1   = (const float*)d_in[7];
    const float* bs1   = (const float*)d_in[8];
    const float* Ws2   = (const float*)d_in[9];
    const float* bs2   = (const float*)d_in[10];
    const float* Wa    = (const float*)d_in[11];
    const float* ba    = (const float*)d_in[12];

    float* out_u = (float*)d_out;            // (64, 1024)
    float* outA  = out_u + BATCH * DU;       // (64, 2048)

    k_setup<<<4, 1024>>>(Ws1, bs1, vn);
    k_prep<<<(DU * DMODEL + 255) / 256, 256>>>(Wa, Ws1, out_u);

    k_emb<<<NTOK / 16, 256>>>(q_seq, r_seq, t_seq, q_tab, r_tab);

    cudaFuncSetAttribute(k_logits_mma, cudaFuncAttributeMaxDynamicSharedMemorySize, SMEM_LG);
    k_logits_mma<<<148, 512, SMEM_LG>>>(mask, Ws2, bs2, outA);

    cudaFuncSetAttribute(k_agg_p, cudaFuncAttributeMaxDynamicSharedMemorySize, SMEM_AGG);
    k_agg_p<<<dim3(8, 16), 512, SMEM_AGG>>>(ba, out_u);
}